// round 1
// baseline (speedup 1.0000x reference)
#include <cuda_runtime.h>
#include <cstdint>
#include <cstddef>

static constexpr int Bn = 8;
static constexpr int Cc = 512;
static constexpr int Nn = 4096;   // H*W
static constexpr int Kd = 64;
static constexpr int Vd = 512;

// Scratch (device globals: allocation-free per harness rules)
__device__ float g_Q [(size_t)Bn * Nn * Kd];   // [b][n][k]   8 MB
__device__ float g_Km[(size_t)Bn * Nn * Kd];   // [b][m][k]   8 MB
__device__ float g_Vm[(size_t)Bn * Nn * Vd];   // [b][m][v]  67 MB
__device__ float g_P [(size_t)Bn * Nn * Nn];   // exp(energy) [b][n][m]  537 MB
__device__ float g_L [(size_t)Bn * Nn];        // row sums of exp
__device__ float g_scl[Vd];
__device__ float g_shf[Vd];

// ---------------------------------------------------------------------------
// BN scale/shift precompute
// ---------------------------------------------------------------------------
__global__ void prep_kernel(const float* __restrict__ gamma, const float* __restrict__ beta,
                            const float* __restrict__ mean,  const float* __restrict__ var) {
    int i = threadIdx.x;
    if (i < Vd) {
        float s = gamma[i] * rsqrtf(var[i] + 1e-5f);
        g_scl[i] = s;
        g_shf[i] = beta[i] - mean[i] * s;
    }
}

// ---------------------------------------------------------------------------
// Projection: out[b][n][o] = epi( sum_c W[o][c] * x[b][c][n] )
//   epi: val*scl[o] + shf[o], optional relu. (scl==nullptr -> scale 1)
// grid: (Nn/64, Odim/64, B), block 256
// ---------------------------------------------------------------------------
__global__ __launch_bounds__(256) void proj_kernel(
    const float* __restrict__ x, const float* __restrict__ W,
    const float* __restrict__ scl, const float* __restrict__ shf,
    float* __restrict__ out, int Odim, int relu) {
    __shared__ float Xs[16][65];   // [c_local][n_local]
    __shared__ float Ws[64][17];   // [o_local][c_local]
    const int b  = blockIdx.z;
    const int n0 = blockIdx.x * 64;
    const int o0 = blockIdx.y * 64;
    const int tid = threadIdx.x;
    const int tx = tid & 15, ty = tid >> 4;

    float acc[4][4] = {};
    const float* xb = x + (size_t)b * Cc * Nn;

    for (int c0 = 0; c0 < Cc; c0 += 16) {
        {
            int n_l = tid & 63, c_l = tid >> 6;
            #pragma unroll
            for (int it = 0; it < 4; it++)
                Xs[c_l + 4 * it][n_l] = xb[(size_t)(c0 + c_l + 4 * it) * Nn + n0 + n_l];
        }
        {
            int c_l = tid & 15, o_l = tid >> 4;
            #pragma unroll
            for (int it = 0; it < 4; it++)
                Ws[o_l + 16 * it][c_l] = W[(size_t)(o0 + o_l + 16 * it) * Cc + c0 + c_l];
        }
        __syncthreads();
        #pragma unroll
        for (int cc = 0; cc < 16; cc++) {
            float a[4], w[4];
            #pragma unroll
            for (int i = 0; i < 4; i++) a[i] = Xs[cc][ty + 16 * i];
            #pragma unroll
            for (int j = 0; j < 4; j++) w[j] = Ws[tx + 16 * j][cc];
            #pragma unroll
            for (int i = 0; i < 4; i++)
                #pragma unroll
                for (int j = 0; j < 4; j++)
                    acc[i][j] = fmaf(a[i], w[j], acc[i][j]);
        }
        __syncthreads();
    }

    #pragma unroll
    for (int i = 0; i < 4; i++) {
        int n = n0 + ty + 16 * i;
        #pragma unroll
        for (int j = 0; j < 4; j++) {
            int o = o0 + tx + 16 * j;
            float s = scl ? scl[o] : 1.0f;
            float v = fmaf(acc[i][j], s, shf[o]);
            if (relu) v = fmaxf(v, 0.0f);
            out[((size_t)b * Nn + n) * Odim + o] = v;   // coalesced along o (tx)
        }
    }
}

// ---------------------------------------------------------------------------
// Energy + exp + row sums.
//   g_P[b][n][m] = exp( Q[b][n] . K[b][m] ),  g_L[b][n] = sum_m g_P[b][n][m]
// No max-subtraction: logits ~N(0,8), max ~44 -> exp <= ~1.3e19, fp32-safe.
// grid: (Nn/64, B), block 256; tile 64 queries x 64 keys, 4x4 micro-tile.
// ---------------------------------------------------------------------------
__global__ __launch_bounds__(256) void energy_kernel() {
    __shared__ float Qs[64][65];
    __shared__ float Ks[64][65];
    const int b  = blockIdx.y;
    const int n0 = blockIdx.x * 64;
    const int tid = threadIdx.x;
    const int tx = tid & 15, ty = tid >> 4;   // tx -> key cols, ty -> query rows

    {
        int d = tid & 63, r = tid >> 6;
        #pragma unroll
        for (int it = 0; it < 16; it++)
            Qs[r + 4 * it][d] = g_Q[((size_t)b * Nn + n0 + r + 4 * it) * Kd + d];
    }

    float rsum[4] = {0.f, 0.f, 0.f, 0.f};

    for (int m0 = 0; m0 < Nn; m0 += 64) {
        __syncthreads();   // previous tile's Ks fully consumed (also covers Qs on iter 0)
        {
            int d = tid & 63, r = tid >> 6;
            #pragma unroll
            for (int it = 0; it < 16; it++)
                Ks[r + 4 * it][d] = g_Km[((size_t)b * Nn + m0 + r + 4 * it) * Kd + d];
        }
        __syncthreads();

        float acc[4][4] = {};
        #pragma unroll 16
        for (int d = 0; d < 64; d++) {
            float q[4], k[4];
            #pragma unroll
            for (int i = 0; i < 4; i++) q[i] = Qs[ty + 16 * i][d];
            #pragma unroll
            for (int j = 0; j < 4; j++) k[j] = Ks[tx + 16 * j][d];
            #pragma unroll
            for (int i = 0; i < 4; i++)
                #pragma unroll
                for (int j = 0; j < 4; j++)
                    acc[i][j] = fmaf(q[i], k[j], acc[i][j]);
        }

        #pragma unroll
        for (int i = 0; i < 4; i++) {
            size_t row = ((size_t)b * Nn + n0 + ty + 16 * i) * Nn + m0;
            #pragma unroll
            for (int j = 0; j < 4; j++) {
                float e = __expf(acc[i][j]);
                rsum[i] += e;
                g_P[row + tx + 16 * j] = e;
            }
        }
    }

    // row (ty,i) uniquely owned across ty*i; reduce over the 16 tx lanes
    #pragma unroll
    for (int i = 0; i < 4; i++) {
        float v = rsum[i];
        #pragma unroll
        for (int off = 8; off > 0; off >>= 1)
            v += __shfl_down_sync(0xffffffffu, v, off, 16);
        if (tx == 0) g_L[(size_t)b * Nn + n0 + ty + 16 * i] = v;
    }
}

// ---------------------------------------------------------------------------
// out[b][v][n] = (1/g_L[b][n]) * sum_m g_P[b][n][m] * g_Vm[b][m][v]
// grid: (Vd/128, Nn/128, B), block 256; 128x128 tile, K-chunk 32, 8x8 micro.
// ---------------------------------------------------------------------------
__global__ __launch_bounds__(256) void av_gemm_kernel(float* __restrict__ out) {
    __shared__ float Ps[32][129];   // [m_local][n_local] (transposed on load)
    __shared__ float Vs[32][129];   // [m_local][v_local]
    const int b  = blockIdx.z;
    const int n0 = blockIdx.y * 128;
    const int v0 = blockIdx.x * 128;
    const int tid = threadIdx.x;
    const int tx = tid & 15, ty = tid >> 4;  // tx -> n (coalesced out), ty -> v

    float acc[8][8] = {};   // [i over n][j over v]

    for (int m0 = 0; m0 < Nn; m0 += 32) {
        __syncthreads();
        {
            int m_l = tid & 31, n_l0 = tid >> 5;
            const float* p = &g_P[((size_t)b * Nn + n0 + n_l0) * Nn + m0 + m_l];
            #pragma unroll
            for (int it = 0; it < 16; it++)
                Ps[m_l][n_l0 + 8 * it] = p[(size_t)(8 * it) * Nn];
        }
        {
            int v_l = tid & 127, m_l0 = tid >> 7;
            const float* vv = &g_Vm[((size_t)b * Nn + m0 + m_l0) * Vd + v0 + v_l];
            #pragma unroll
            for (int it = 0; it < 16; it++)
                Vs[m_l0 + 2 * it][v_l] = vv[(size_t)(2 * it) * Vd];
        }
        __syncthreads();

        #pragma unroll 4
        for (int mc = 0; mc < 32; mc++) {
            float pr[8], vr[8];
            #pragma unroll
            for (int i = 0; i < 8; i++) pr[i] = Ps[mc][tx + 16 * i];
            #pragma unroll
            for (int j = 0; j < 8; j++) vr[j] = Vs[mc][ty + 16 * j];
            #pragma unroll
            for (int i = 0; i < 8; i++)
                #pragma unroll
                for (int j = 0; j < 8; j++)
                    acc[i][j] = fmaf(pr[i], vr[j], acc[i][j]);
        }
    }

    float linv[8];
    #pragma unroll
    for (int i = 0; i < 8; i++)
        linv[i] = 1.0f / g_L[(size_t)b * Nn + n0 + tx + 16 * i];

    #pragma unroll
    for (int j = 0; j < 8; j++) {
        int v = v0 + ty + 16 * j;
        float* op = out + ((size_t)b * Vd + v) * Nn + n0 + tx;
        #pragma unroll
        for (int i = 0; i < 8; i++)
            op[16 * i] = acc[i][j] * linv[i];   // coalesced along n (tx)
    }
}

// ---------------------------------------------------------------------------
extern "C" void kernel_launch(void* const* d_in, const int* in_sizes, int n_in,
                              void* d_out, int out_size) {
    const float* x     = (const float*)d_in[0];
    const float* Wq    = (const float*)d_in[1];
    const float* bq    = (const float*)d_in[2];
    const float* Wk    = (const float*)d_in[3];
    const float* bk    = (const float*)d_in[4];
    const float* Wv    = (const float*)d_in[5];
    const float* gamma = (const float*)d_in[6];
    const float* beta  = (const float*)d_in[7];
    const float* mean  = (const float*)d_in[8];
    const float* var   = (const float*)d_in[9];
    float* out = (float*)d_out;

    float *Qp, *Kp, *Vp, *sclp, *shfp;
    cudaGetSymbolAddress((void**)&Qp,   g_Q);
    cudaGetSymbolAddress((void**)&Kp,   g_Km);
    cudaGetSymbolAddress((void**)&Vp,   g_Vm);
    cudaGetSymbolAddress((void**)&sclp, g_scl);
    cudaGetSymbolAddress((void**)&shfp, g_shf);

    prep_kernel<<<1, 512>>>(gamma, beta, mean, var);

    proj_kernel<<<dim3(Nn / 64, Kd / 64, Bn), 256>>>(x, Wq, nullptr, bq, Qp, Kd, 0);
    proj_kernel<<<dim3(Nn / 64, Kd / 64, Bn), 256>>>(x, Wk, nullptr, bk, Kp, Kd, 0);
    proj_kernel<<<dim3(Nn / 64, Vd / 64, Bn), 256>>>(x, Wv, sclp, shfp, Vp, Vd, 1);

    energy_kernel<<<dim3(Nn / 64, Bn), 256>>>();

    av_gemm_kernel<<<dim3(Vd / 128, Nn / 128, Bn), 256>>>(out);
}

// round 3
// speedup vs baseline: 1.9122x; 1.9122x over previous
#include <cuda_runtime.h>
#include <cstdint>
#include <cstddef>

static constexpr int Bn = 8;
static constexpr int Cc = 512;
static constexpr int Nn = 4096;   // H*W
static constexpr int Kd = 64;
static constexpr int Vd = 512;

// Scratch (device globals: allocation-free per harness rules)
__device__ float g_Q [(size_t)Bn * Nn * Kd];   // [b][n][k]
__device__ float g_Km[(size_t)Bn * Nn * Kd];   // [b][m][k]
__device__ float g_Vm[(size_t)Bn * Nn * Vd];   // [b][m][v]
__device__ float g_P [(size_t)Bn * Nn * Nn];   // exp(energy) [b][n][m]
__device__ float g_L [(size_t)Bn * Nn];        // row sums of exp
__device__ float g_scl[Vd];
__device__ float g_shf[Vd];

// ===========================================================================
// Helpers (portable ISA only: sm_80-class mma.sync + cp.async; NO `a` features)
// ===========================================================================
__device__ __forceinline__ uint32_t smem_u32(const void* p) {
    uint32_t a;
    asm("{ .reg .u64 t; cvta.to.shared.u64 t, %1; cvt.u32.u64 %0, t; }" : "=r"(a) : "l"(p));
    return a;
}
__device__ __forceinline__ uint32_t f2tf32(float x) {   // round-to-nearest tf32
    uint32_t u;
    asm("cvt.rna.tf32.f32 %0, %1;" : "=r"(u) : "f"(x));
    return u;
}
__device__ __forceinline__ void cp_async16(uint32_t saddr, const void* gaddr) {
    asm volatile("cp.async.ca.shared.global [%0], [%1], 16;"
                 :: "r"(saddr), "l"(gaddr) : "memory");
}
__device__ __forceinline__ void cp_commit() {
    asm volatile("cp.async.commit_group;" ::: "memory");
}
__device__ __forceinline__ void cp_wait1() {
    asm volatile("cp.async.wait_group 1;" ::: "memory");
}
__device__ __forceinline__ void cp_wait0() {
    asm volatile("cp.async.wait_group 0;" ::: "memory");
}
// D += A * B  (m16n8k8, A row-major 16x8, B col-major 8x8, tf32 in, f32 acc)
__device__ __forceinline__ void mma_tf32(float* d, const uint32_t* a, const uint32_t* b) {
    asm volatile(
        "mma.sync.aligned.m16n8k8.row.col.f32.tf32.tf32.f32 "
        "{%0,%1,%2,%3}, {%4,%5,%6,%7}, {%8,%9}, {%0,%1,%2,%3};"
        : "+f"(d[0]), "+f"(d[1]), "+f"(d[2]), "+f"(d[3])
        : "r"(a[0]), "r"(a[1]), "r"(a[2]), "r"(a[3]), "r"(b[0]), "r"(b[1]));
}

// ===========================================================================
// BN scale/shift precompute
// ===========================================================================
__global__ void prep_kernel(const float* __restrict__ gamma, const float* __restrict__ beta,
                            const float* __restrict__ mean,  const float* __restrict__ var) {
    int i = threadIdx.x;
    if (i < Vd) {
        float s = gamma[i] * rsqrtf(var[i] + 1e-5f);
        g_scl[i] = s;
        g_shf[i] = beta[i] - mean[i] * s;
    }
}

// ===========================================================================
// Projection: out[b][n][o] = epi( sum_c W[o][c] * x[b][c][n] )
// ===========================================================================
__global__ __launch_bounds__(256) void proj_kernel(
    const float* __restrict__ x, const float* __restrict__ W,
    const float* __restrict__ scl, const float* __restrict__ shf,
    float* __restrict__ out, int Odim, int relu) {
    __shared__ float Xs[16][65];
    __shared__ float Ws[64][17];
    const int b  = blockIdx.z;
    const int n0 = blockIdx.x * 64;
    const int o0 = blockIdx.y * 64;
    const int tid = threadIdx.x;
    const int tx = tid & 15, ty = tid >> 4;

    float acc[4][4] = {};
    const float* xb = x + (size_t)b * Cc * Nn;

    for (int c0 = 0; c0 < Cc; c0 += 16) {
        {
            int n_l = tid & 63, c_l = tid >> 6;
            #pragma unroll
            for (int it = 0; it < 4; it++)
                Xs[c_l + 4 * it][n_l] = xb[(size_t)(c0 + c_l + 4 * it) * Nn + n0 + n_l];
        }
        {
            int c_l = tid & 15, o_l = tid >> 4;
            #pragma unroll
            for (int it = 0; it < 4; it++)
                Ws[o_l + 16 * it][c_l] = W[(size_t)(o0 + o_l + 16 * it) * Cc + c0 + c_l];
        }
        __syncthreads();
        #pragma unroll
        for (int cc = 0; cc < 16; cc++) {
            float a[4], w[4];
            #pragma unroll
            for (int i = 0; i < 4; i++) a[i] = Xs[cc][ty + 16 * i];
            #pragma unroll
            for (int j = 0; j < 4; j++) w[j] = Ws[tx + 16 * j][cc];
            #pragma unroll
            for (int i = 0; i < 4; i++)
                #pragma unroll
                for (int j = 0; j < 4; j++)
                    acc[i][j] = fmaf(a[i], w[j], acc[i][j]);
        }
        __syncthreads();
    }

    #pragma unroll
    for (int i = 0; i < 4; i++) {
        int n = n0 + ty + 16 * i;
        #pragma unroll
        for (int j = 0; j < 4; j++) {
            int o = o0 + tx + 16 * j;
            float s = scl ? scl[o] : 1.0f;
            float v = fmaf(acc[i][j], s, shf[o]);
            if (relu) v = fmaxf(v, 0.0f);
            out[((size_t)b * Nn + n) * Odim + o] = v;
        }
    }
}

// ===========================================================================
// Energy + exp + row sums (fp32 SIMT)
// ===========================================================================
__global__ __launch_bounds__(256) void energy_kernel() {
    __shared__ float Qs[64][65];
    __shared__ float Ks[64][65];
    const int b  = blockIdx.y;
    const int n0 = blockIdx.x * 64;
    const int tid = threadIdx.x;
    const int tx = tid & 15, ty = tid >> 4;

    {
        int d = tid & 63, r = tid >> 6;
        #pragma unroll
        for (int it = 0; it < 16; it++)
            Qs[r + 4 * it][d] = g_Q[((size_t)b * Nn + n0 + r + 4 * it) * Kd + d];
    }

    float rsum[4] = {0.f, 0.f, 0.f, 0.f};

    for (int m0 = 0; m0 < Nn; m0 += 64) {
        __syncthreads();
        {
            int d = tid & 63, r = tid >> 6;
            #pragma unroll
            for (int it = 0; it < 16; it++)
                Ks[r + 4 * it][d] = g_Km[((size_t)b * Nn + m0 + r + 4 * it) * Kd + d];
        }
        __syncthreads();

        float acc[4][4] = {};
        #pragma unroll 16
        for (int d = 0; d < 64; d++) {
            float q[4], k[4];
            #pragma unroll
            for (int i = 0; i < 4; i++) q[i] = Qs[ty + 16 * i][d];
            #pragma unroll
            for (int j = 0; j < 4; j++) k[j] = Ks[tx + 16 * j][d];
            #pragma unroll
            for (int i = 0; i < 4; i++)
                #pragma unroll
                for (int j = 0; j < 4; j++)
                    acc[i][j] = fmaf(q[i], k[j], acc[i][j]);
        }

        #pragma unroll
        for (int i = 0; i < 4; i++) {
            size_t row = ((size_t)b * Nn + n0 + ty + 16 * i) * Nn + m0;
            #pragma unroll
            for (int j = 0; j < 4; j++) {
                float e = __expf(acc[i][j]);
                rsum[i] += e;
                g_P[row + tx + 16 * j] = e;
            }
        }
    }

    #pragma unroll
    for (int i = 0; i < 4; i++) {
        float v = rsum[i];
        #pragma unroll
        for (int off = 8; off > 0; off >>= 1)
            v += __shfl_down_sync(0xffffffffu, v, off, 16);
        if (tx == 0) g_L[(size_t)b * Nn + n0 + ty + 16 * i] = v;
    }
}

// ===========================================================================
// PV GEMM via mma.sync tf32:
//   out[b][v][n] = (1/L[n]) * sum_m P[n][m] * Vm[m][v]
// CTA tile 128(n) x 128(v) x 32(m); 8 warps (2 in n x 4 in v), warp 64x32.
// SMEM: A as [n][k] stride 36 (36%32==4 -> conflict-free fragment loads),
//       B as [k][v] stride 136 (136%32==8 -> conflict-free), cp.async x2 buf.
// ===========================================================================
static constexpr int BM = 128, BNv = 128, BK = 32;
static constexpr int N_CH = Nn / BK;           // 128
static constexpr int SA_STR = 36;              // floats per A row
static constexpr int SB_STR = 136;             // floats per B row
static constexpr int OFA0 = 0;
static constexpr int OFA1 = BM * SA_STR;                 // 4608 floats
static constexpr int OFB0 = 2 * BM * SA_STR;             // 9216
static constexpr int OFB1 = OFB0 + BK * SB_STR;          // 13568
static constexpr int SM_FLOATS = OFB1 + BK * SB_STR;     // 17920 floats = 71680 B

__device__ __forceinline__ void stage_tiles(uint32_t sbase, int buf,
                                            const float* pA, const float* pB) {
    const int t = threadIdx.x;
    const uint32_t sA = sbase + (buf ? OFA1 : OFA0) * 4;
    const uint32_t sB = sbase + (buf ? OFB1 : OFB0) * 4;
    {
        int c4 = t & 7, r0 = t >> 3;              // 8 float4 per 32-float row
        #pragma unroll
        for (int p = 0; p < 4; p++) {
            int r = r0 + 32 * p;
            cp_async16(sA + (uint32_t)(r * SA_STR + c4 * 4) * 4,
                       pA + (size_t)r * Nn + c4 * 4);
        }
    }
    {
        int c4 = t & 31, k0 = t >> 5;             // 32 float4 per 128-float row
        #pragma unroll
        for (int p = 0; p < 4; p++) {
            int k = k0 + 8 * p;
            cp_async16(sB + (uint32_t)(k * SB_STR + c4 * 4) * 4,
                       pB + (size_t)k * Vd + c4 * 4);
        }
    }
}

__global__ __launch_bounds__(256) void av_mma_kernel(float* __restrict__ out) {
    extern __shared__ float sm[];
    const uint32_t sbase = smem_u32(sm);
    const int tid  = threadIdx.x;
    const int wid  = tid >> 5, lane = tid & 31;
    const int g = lane >> 2, c = lane & 3;        // fragment group / thread-in-group
    const int wn = wid & 1;                       // warp n-tile (0..1) of 64
    const int wv = wid >> 1;                      // warp v-tile (0..3) of 32
    const int b  = blockIdx.z;
    const int n0 = blockIdx.y * BM;
    const int v0 = blockIdx.x * BNv;

    const float* pA = g_P  + ((size_t)b * Nn + n0) * Nn;   // [n][m], stride Nn
    const float* pB = g_Vm + ((size_t)b * Nn) * Vd + v0;   // [m][v], stride Vd

    float acc[4][4][4] = {};                      // [rowtile][coltile][frag]

    stage_tiles(sbase, 0, pA, pB);
    cp_commit();

    for (int it = 0; it < N_CH; it++) {
        const int cur = it & 1;
        if (it + 1 < N_CH) {
            stage_tiles(sbase, cur ^ 1, pA + (size_t)(it + 1) * BK,
                        pB + (size_t)(it + 1) * BK * Vd);
            cp_commit();
            cp_wait1();
        } else {
            cp_wait0();
        }
        __syncthreads();

        const float* As = sm + (cur ? OFA1 : OFA0);
        const float* Bs = sm + (cur ? OFB1 : OFB0);

        #pragma unroll
        for (int ks = 0; ks < 4; ks++) {          // 4 x k8 steps
            uint32_t af[4][4];
            #pragma unroll
            for (int i = 0; i < 4; i++) {
                const float* ap = As + (wn * 64 + i * 16 + g) * SA_STR + ks * 8 + c;
                af[i][0] = f2tf32(ap[0]);
                af[i][1] = f2tf32(ap[8 * SA_STR]);
                af[i][2] = f2tf32(ap[4]);
                af[i][3] = f2tf32(ap[8 * SA_STR + 4]);
            }
            uint32_t bf[4][2];
            #pragma unroll
            for (int j = 0; j < 4; j++) {
                const float* bp = Bs + (ks * 8 + c) * SB_STR + wv * 32 + j * 8 + g;
                bf[j][0] = f2tf32(bp[0]);
                bf[j][1] = f2tf32(bp[4 * SB_STR]);
            }
            #pragma unroll
            for (int i = 0; i < 4; i++)
                #pragma unroll
                for (int j = 0; j < 4; j++)
                    mma_tf32(acc[i][j], af[i], bf[j]);
        }
        __syncthreads();
    }

    // Epilogue: scale by 1/L[n], store out[b][v][n]
    #pragma unroll
    for (int i = 0; i < 4; i++) {
        const int n_lo = n0 + wn * 64 + i * 16 + g;
        const float linv_lo = 1.0f / g_L[(size_t)b * Nn + n_lo];
        const float linv_hi = 1.0f / g_L[(size_t)b * Nn + n_lo + 8];
        #pragma unroll
        for (int j = 0; j < 4; j++) {
            const int v = v0 + wv * 32 + j * 8 + c * 2;
            float* o0p = out + ((size_t)b * Vd + v)     * Nn + n_lo;
            float* o1p = out + ((size_t)b * Vd + v + 1) * Nn + n_lo;
            o0p[0] = acc[i][j][0] * linv_lo;
            o1p[0] = acc[i][j][1] * linv_lo;
            o0p[8] = acc[i][j][2] * linv_hi;
            o1p[8] = acc[i][j][3] * linv_hi;
        }
    }
}

// ===========================================================================
extern "C" void kernel_launch(void* const* d_in, const int* in_sizes, int n_in,
                              void* d_out, int out_size) {
    const float* x     = (const float*)d_in[0];
    const float* Wq    = (const float*)d_in[1];
    const float* bq    = (const float*)d_in[2];
    const float* Wk    = (const float*)d_in[3];
    const float* bk    = (const float*)d_in[4];
    const float* Wv    = (const float*)d_in[5];
    const float* gamma = (const float*)d_in[6];
    const float* beta  = (const float*)d_in[7];
    const float* mean  = (const float*)d_in[8];
    const float* var   = (const float*)d_in[9];
    float* out = (float*)d_out;

    float *Qp, *Kp, *Vp, *sclp, *shfp;
    cudaGetSymbolAddress((void**)&Qp,   g_Q);
    cudaGetSymbolAddress((void**)&Kp,   g_Km);
    cudaGetSymbolAddress((void**)&Vp,   g_Vm);
    cudaGetSymbolAddress((void**)&sclp, g_scl);
    cudaGetSymbolAddress((void**)&shfp, g_shf);

    static int smem_set = 0;
    if (!smem_set) {
        cudaFuncSetAttribute(av_mma_kernel,
                             cudaFuncAttributeMaxDynamicSharedMemorySize,
                             SM_FLOATS * 4);
        smem_set = 1;
    }

    prep_kernel<<<1, 512>>>(gamma, beta, mean, var);

    proj_kernel<<<dim3(Nn / 64, Kd / 64, Bn), 256>>>(x, Wq, nullptr, bq, Qp, Kd, 0);
    proj_kernel<<<dim3(Nn / 64, Kd / 64, Bn), 256>>>(x, Wk, nullptr, bk, Kp, Kd, 0);
    proj_kernel<<<dim3(Nn / 64, Vd / 64, Bn), 256>>>(x, Wv, sclp, shfp, Vp, Vd, 1);

    energy_kernel<<<dim3(Nn / 64, Bn), 256>>>();

    av_mma_kernel<<<dim3(Vd / BNv, Nn / BM, Bn), 256, SM_FLOATS * 4>>>(out);
}

// round 4
// speedup vs baseline: 3.0352x; 1.5873x over previous
#include <cuda_runtime.h>
#include <cstdint>
#include <cstddef>

static constexpr int Bn = 8;
static constexpr int Cc = 512;
static constexpr int Nn = 4096;   // H*W
static constexpr int Kd = 64;
static constexpr int Vd = 512;

// Scratch (device globals: allocation-free per harness rules)
__device__ float g_Qh[(size_t)Bn * Nn * Kd];   // [b][n][k] tf32 hi
__device__ float g_Ql[(size_t)Bn * Nn * Kd];   // residual lo
__device__ float g_Kh[(size_t)Bn * Nn * Kd];
__device__ float g_Kl[(size_t)Bn * Nn * Kd];
__device__ float g_Vm[(size_t)Bn * Nn * Vd];   // [b][m][v], tf32-rounded
__device__ float g_P [(size_t)Bn * Nn * Nn];   // exp(energy), tf32-rounded
__device__ float g_L [(size_t)Bn * Nn];        // row sums
__device__ float g_scl[Vd];
__device__ float g_shf[Vd];

// ===========================================================================
// Helpers (portable ISA: sm_80-class mma.sync + cp.async only)
// ===========================================================================
__device__ __forceinline__ uint32_t smem_u32(const void* p) {
    uint32_t a;
    asm("{ .reg .u64 t; cvta.to.shared.u64 t, %1; cvt.u32.u64 %0, t; }" : "=r"(a) : "l"(p));
    return a;
}
__device__ __forceinline__ uint32_t f2tf32(float x) {   // round-to-nearest tf32
    uint32_t u;
    asm("cvt.rna.tf32.f32 %0, %1;" : "=r"(u) : "f"(x));
    return u;
}
__device__ __forceinline__ float tf32r(float x) { return __uint_as_float(f2tf32(x)); }
__device__ __forceinline__ void cp_async16(uint32_t saddr, const void* gaddr) {
    asm volatile("cp.async.ca.shared.global [%0], [%1], 16;"
                 :: "r"(saddr), "l"(gaddr) : "memory");
}
__device__ __forceinline__ void cp_commit() {
    asm volatile("cp.async.commit_group;" ::: "memory");
}
__device__ __forceinline__ void cp_wait1() {
    asm volatile("cp.async.wait_group 1;" ::: "memory");
}
__device__ __forceinline__ void cp_wait0() {
    asm volatile("cp.async.wait_group 0;" ::: "memory");
}
__device__ __forceinline__ void mma_tf32(float* d, const uint32_t* a, const uint32_t* b) {
    asm volatile(
        "mma.sync.aligned.m16n8k8.row.col.f32.tf32.tf32.f32 "
        "{%0,%1,%2,%3}, {%4,%5,%6,%7}, {%8,%9}, {%0,%1,%2,%3};"
        : "+f"(d[0]), "+f"(d[1]), "+f"(d[2]), "+f"(d[3])
        : "r"(a[0]), "r"(a[1]), "r"(a[2]), "r"(a[3]), "r"(b[0]), "r"(b[1]));
}
__device__ __forceinline__ uint32_t fu(float x) { return __float_as_uint(x); }

// ===========================================================================
// BN scale/shift precompute
// ===========================================================================
__global__ void prep_kernel(const float* __restrict__ gamma, const float* __restrict__ beta,
                            const float* __restrict__ mean,  const float* __restrict__ var) {
    int i = threadIdx.x;
    if (i < Vd) {
        float s = gamma[i] * rsqrtf(var[i] + 1e-5f);
        g_scl[i] = s;
        g_shf[i] = beta[i] - mean[i] * s;
    }
}

// ===========================================================================
// Q/K projection (SIMT fp32, accurate) -> hi/lo tf32 split outputs
// out_hi/out_lo[b][n][o], Odim = 64. grid (Nn/64, 1, Bn), block 256.
// ===========================================================================
__global__ __launch_bounds__(256) void qk_proj_kernel(
    const float* __restrict__ x, const float* __restrict__ W,
    const float* __restrict__ bias,
    float* __restrict__ out_hi, float* __restrict__ out_lo) {
    __shared__ float Xs[16][65];
    __shared__ float Ws[64][17];
    const int b  = blockIdx.z;
    const int n0 = blockIdx.x * 64;
    const int tid = threadIdx.x;
    const int tx = tid & 15, ty = tid >> 4;

    float acc[4][4] = {};
    const float* xb = x + (size_t)b * Cc * Nn;

    for (int c0 = 0; c0 < Cc; c0 += 16) {
        {
            int n_l = tid & 63, c_l = tid >> 6;
            #pragma unroll
            for (int it = 0; it < 4; it++)
                Xs[c_l + 4 * it][n_l] = xb[(size_t)(c0 + c_l + 4 * it) * Nn + n0 + n_l];
        }
        {
            int c_l = tid & 15, o_l = tid >> 4;
            #pragma unroll
            for (int it = 0; it < 4; it++)
                Ws[o_l + 16 * it][c_l] = W[(size_t)(o_l + 16 * it) * Cc + c0 + c_l];
        }
        __syncthreads();
        #pragma unroll
        for (int cc = 0; cc < 16; cc++) {
            float a[4], w[4];
            #pragma unroll
            for (int i = 0; i < 4; i++) a[i] = Xs[cc][ty + 16 * i];
            #pragma unroll
            for (int j = 0; j < 4; j++) w[j] = Ws[tx + 16 * j][cc];
            #pragma unroll
            for (int i = 0; i < 4; i++)
                #pragma unroll
                for (int j = 0; j < 4; j++)
                    acc[i][j] = fmaf(a[i], w[j], acc[i][j]);
        }
        __syncthreads();
    }

    #pragma unroll
    for (int i = 0; i < 4; i++) {
        int n = n0 + ty + 16 * i;
        #pragma unroll
        for (int j = 0; j < 4; j++) {
            int o = tx + 16 * j;
            float v  = acc[i][j] + bias[o];
            float hi = tf32r(v);
            float lo = tf32r(v - hi);
            size_t idx = ((size_t)b * Nn + n) * Kd + o;
            out_hi[idx] = hi;
            out_lo[idx] = lo;
        }
    }
}

// ===========================================================================
// V projection on mma.sync tf32:
//   g_Vm[b][n][o] = tf32r( relu( (sum_c x[c][n] W[o][c]) * scl[o] + shf[o] ) )
// Tile 128(n) x 128(o) x 32(c); 8 warps 2x4; double-buffered cp.async.
// SMEM: X as [c][n] stride 136, W as [o][c] stride 36.
// ===========================================================================
static constexpr int V_OFX0 = 0;               // 32*136 = 4352 floats
static constexpr int V_OFX1 = 4352;
static constexpr int V_OFW0 = 8704;            // 128*36 = 4608 floats
static constexpr int V_OFW1 = 13312;
static constexpr int V_FLOATS = 17920;         // 71.7 KB

__device__ __forceinline__ void vproj_stage(uint32_t sbase, int buf,
                                            const float* xb, const float* W,
                                            int n0, int v0, int kc) {
    const int t = threadIdx.x;
    const uint32_t sX = sbase + (buf ? V_OFX1 : V_OFX0) * 4;
    const uint32_t sW = sbase + (buf ? V_OFW1 : V_OFW0) * 4;
    #pragma unroll
    for (int p = 0; p < 4; p++) {                 // X: 32 rows(c) x 32 f4
        int id = t + 256 * p, r = id >> 5, c4 = id & 31;
        cp_async16(sX + (uint32_t)(r * 136 + c4 * 4) * 4,
                   xb + (size_t)(kc * 32 + r) * Nn + n0 + c4 * 4);
    }
    #pragma unroll
    for (int p = 0; p < 4; p++) {                 // W: 128 rows(o) x 8 f4
        int id = t + 256 * p, r = id >> 3, c4 = id & 7;
        cp_async16(sW + (uint32_t)(r * 36 + c4 * 4) * 4,
                   W + (size_t)(v0 + r) * Cc + kc * 32 + c4 * 4);
    }
}

__global__ __launch_bounds__(256) void vproj_mma_kernel(const float* __restrict__ x,
                                                        const float* __restrict__ W) {
    extern __shared__ float sm[];
    const uint32_t sbase = smem_u32(sm);
    const int tid = threadIdx.x;
    const int wid = tid >> 5, lane = tid & 31;
    const int g = lane >> 2, c = lane & 3;
    const int wn = wid & 1, wv = wid >> 1;
    const int b  = blockIdx.z;
    const int n0 = blockIdx.y * 128;
    const int v0 = blockIdx.x * 128;
    const float* xb = x + (size_t)b * Cc * Nn;

    float acc[4][4][4] = {};

    vproj_stage(sbase, 0, xb, W, n0, v0, 0);
    cp_commit();

    for (int kc = 0; kc < Cc / 32; kc++) {
        const int cur = kc & 1;
        if (kc + 1 < Cc / 32) {
            vproj_stage(sbase, cur ^ 1, xb, W, n0, v0, kc + 1);
            cp_commit();
            cp_wait1();
        } else {
            cp_wait0();
        }
        __syncthreads();

        const float* Xs = sm + (cur ? V_OFX1 : V_OFX0);
        const float* Ws = sm + (cur ? V_OFW1 : V_OFW0);

        #pragma unroll
        for (int ks = 0; ks < 4; ks++) {
            uint32_t af[4][4];
            #pragma unroll
            for (int i = 0; i < 4; i++) {
                const float* ap = Xs + (ks * 8 + c) * 136 + wn * 64 + i * 16 + g;
                af[i][0] = f2tf32(ap[0]);
                af[i][1] = f2tf32(ap[8]);
                af[i][2] = f2tf32(ap[4 * 136]);
                af[i][3] = f2tf32(ap[4 * 136 + 8]);
            }
            uint32_t bf[4][2];
            #pragma unroll
            for (int j = 0; j < 4; j++) {
                const float* bp = Ws + (wv * 32 + j * 8 + g) * 36 + ks * 8 + c;
                bf[j][0] = f2tf32(bp[0]);
                bf[j][1] = f2tf32(bp[4]);
            }
            #pragma unroll
            for (int i = 0; i < 4; i++)
                #pragma unroll
                for (int j = 0; j < 4; j++)
                    mma_tf32(acc[i][j], af[i], bf[j]);
        }
        __syncthreads();
    }

    #pragma unroll
    for (int j = 0; j < 4; j++) {
        const int o = v0 + wv * 32 + j * 8 + c * 2;
        const float s0 = g_scl[o],     h0 = g_shf[o];
        const float s1 = g_scl[o + 1], h1 = g_shf[o + 1];
        #pragma unroll
        for (int i = 0; i < 4; i++) {
            const int n = n0 + wn * 64 + i * 16 + g;
            float2 lo = { tf32r(fmaxf(fmaf(acc[i][j][0], s0, h0), 0.0f)),
                          tf32r(fmaxf(fmaf(acc[i][j][1], s1, h1), 0.0f)) };
            float2 hi = { tf32r(fmaxf(fmaf(acc[i][j][2], s0, h0), 0.0f)),
                          tf32r(fmaxf(fmaf(acc[i][j][3], s1, h1), 0.0f)) };
            *(float2*)&g_Vm[((size_t)b * Nn + n)     * Vd + o] = lo;
            *(float2*)&g_Vm[((size_t)b * Nn + n + 8) * Vd + o] = hi;
        }
    }
}

// ===========================================================================
// Energy on mma.sync tf32 with 3-term hi/lo split (fp32-accurate logits):
//   g_P[b][n][m] = tf32r(exp(q.k)), g_L[b][n] = sum_m
// Block: 128 n-rows x all m (chunks of 64). Q resident, K single-buffered.
// grid (Nn/128, Bn), block 256, warps 2(n) x 4(m).
// ===========================================================================
static constexpr int E_OFQH = 0;               // 128*68
static constexpr int E_OFQL = 8704;
static constexpr int E_OFKH = 17408;           // 64*68
static constexpr int E_OFKL = 21760;
static constexpr int E_FLOATS = 26112;         // 104.4 KB

__global__ __launch_bounds__(256) void energy_mma_kernel() {
    extern __shared__ float sm[];
    __shared__ float sL[4][128];
    const uint32_t sbase = smem_u32(sm);
    const int tid = threadIdx.x;
    const int wid = tid >> 5, lane = tid & 31;
    const int g = lane >> 2, c = lane & 3;
    const int wn = wid & 1, wv = wid >> 1;
    const int b  = blockIdx.y;
    const int n0 = blockIdx.x * 128;

    const size_t qoff = ((size_t)b * Nn + n0) * Kd;
    #pragma unroll
    for (int p = 0; p < 8; p++) {                 // Q: 128 rows x 16 f4 (hi+lo)
        int id = tid + 256 * p, r = id >> 4, c4 = id & 15;
        cp_async16(sbase + (uint32_t)(E_OFQH + r * 68 + c4 * 4) * 4, g_Qh + qoff + (size_t)r * Kd + c4 * 4);
        cp_async16(sbase + (uint32_t)(E_OFQL + r * 68 + c4 * 4) * 4, g_Ql + qoff + (size_t)r * Kd + c4 * 4);
    }
    cp_commit();

    float rsum[4][2] = {};
    const size_t koff = (size_t)b * Nn * Kd;

    for (int mc = 0; mc < Nn / 64; mc++) {
        __syncthreads();                           // K buffer free
        #pragma unroll
        for (int p = 0; p < 4; p++) {              // K chunk: 64 rows x 16 f4 (hi+lo)
            int id = tid + 256 * p, r = id >> 4, c4 = id & 15;
            cp_async16(sbase + (uint32_t)(E_OFKH + r * 68 + c4 * 4) * 4,
                       g_Kh + koff + (size_t)(mc * 64 + r) * Kd + c4 * 4);
            cp_async16(sbase + (uint32_t)(E_OFKL + r * 68 + c4 * 4) * 4,
                       g_Kl + koff + (size_t)(mc * 64 + r) * Kd + c4 * 4);
        }
        cp_commit(); cp_wait0(); __syncthreads();

        float acc[4][2][4] = {};
        #pragma unroll
        for (int ks = 0; ks < 8; ks++) {
            uint32_t ah[4][4], al[4][4];
            #pragma unroll
            for (int i = 0; i < 4; i++) {
                const int ro = (wn * 64 + i * 16 + g) * 68 + ks * 8 + c;
                const float* hp = sm + E_OFQH + ro;
                const float* lp = sm + E_OFQL + ro;
                ah[i][0] = fu(hp[0]); ah[i][1] = fu(hp[8 * 68]);
                ah[i][2] = fu(hp[4]); ah[i][3] = fu(hp[8 * 68 + 4]);
                al[i][0] = fu(lp[0]); al[i][1] = fu(lp[8 * 68]);
                al[i][2] = fu(lp[4]); al[i][3] = fu(lp[8 * 68 + 4]);
            }
            uint32_t bh[2][2], bl[2][2];
            #pragma unroll
            for (int j = 0; j < 2; j++) {
                const int ro = (wv * 16 + j * 8 + g) * 68 + ks * 8 + c;
                const float* hp = sm + E_OFKH + ro;
                const float* lp = sm + E_OFKL + ro;
                bh[j][0] = fu(hp[0]); bh[j][1] = fu(hp[4]);
                bl[j][0] = fu(lp[0]); bl[j][1] = fu(lp[4]);
            }
            #pragma unroll
            for (int i = 0; i < 4; i++)
                #pragma unroll
                for (int j = 0; j < 2; j++) {
                    mma_tf32(acc[i][j], ah[i], bh[j]);
                    mma_tf32(acc[i][j], ah[i], bl[j]);
                    mma_tf32(acc[i][j], al[i], bh[j]);
                }
        }

        #pragma unroll
        for (int i = 0; i < 4; i++) {
            const int r0 = n0 + wn * 64 + i * 16 + g;
            #pragma unroll
            for (int j = 0; j < 2; j++) {
                const int m = mc * 64 + wv * 16 + j * 8 + c * 2;
                float e00 = tf32r(__expf(acc[i][j][0]));
                float e01 = tf32r(__expf(acc[i][j][1]));
                float e10 = tf32r(__expf(acc[i][j][2]));
                float e11 = tf32r(__expf(acc[i][j][3]));
                *(float2*)&g_P[((size_t)b * Nn + r0)     * Nn + m] = make_float2(e00, e01);
                *(float2*)&g_P[((size_t)b * Nn + r0 + 8) * Nn + m] = make_float2(e10, e11);
                rsum[i][0] += e00 + e01;
                rsum[i][1] += e10 + e11;
            }
        }
    }

    #pragma unroll
    for (int i = 0; i < 4; i++)
        #pragma unroll
        for (int r = 0; r < 2; r++) {
            float v = rsum[i][r];
            v += __shfl_xor_sync(0xffffffffu, v, 1);
            v += __shfl_xor_sync(0xffffffffu, v, 2);
            rsum[i][r] = v;
        }
    if (c == 0) {
        #pragma unroll
        for (int i = 0; i < 4; i++) {
            sL[wv][wn * 64 + i * 16 + g]     = rsum[i][0];
            sL[wv][wn * 64 + i * 16 + g + 8] = rsum[i][1];
        }
    }
    __syncthreads();
    if (tid < 128)
        g_L[(size_t)b * Nn + n0 + tid] = sL[0][tid] + sL[1][tid] + sL[2][tid] + sL[3][tid];
}

// ===========================================================================
// PV GEMM (mma.sync tf32, operands pre-rounded -> no cvt):
//   out[b][v][n] = (1/L[n]) * sum_m P[n][m] Vm[m][v]
// Tile 128(n) x 128(v) x 64(m), double-buffered; warps 2x4.
// ===========================================================================
static constexpr int A_OFA0 = 0;               // 128*68
static constexpr int A_OFA1 = 8704;
static constexpr int A_OFB0 = 17408;           // 64*136
static constexpr int A_OFB1 = 26112;
static constexpr int A_FLOATS = 34816;         // 139.3 KB

__device__ __forceinline__ void av_stage(uint32_t sbase, int buf,
                                         const float* pA, const float* pB, int it) {
    const int t = threadIdx.x;
    const uint32_t sA = sbase + (buf ? A_OFA1 : A_OFA0) * 4;
    const uint32_t sB = sbase + (buf ? A_OFB1 : A_OFB0) * 4;
    #pragma unroll
    for (int p = 0; p < 8; p++) {                 // A: 128 rows(n) x 16 f4
        int id = t + 256 * p, r = id >> 4, c4 = id & 15;
        cp_async16(sA + (uint32_t)(r * 68 + c4 * 4) * 4,
                   pA + (size_t)r * Nn + it * 64 + c4 * 4);
    }
    #pragma unroll
    for (int p = 0; p < 8; p++) {                 // B: 64 rows(m) x 32 f4
        int id = t + 256 * p, r = id >> 5, c4 = id & 31;
        cp_async16(sB + (uint32_t)(r * 136 + c4 * 4) * 4,
                   pB + (size_t)(it * 64 + r) * Vd + c4 * 4);
    }
}

__global__ __launch_bounds__(256) void av_mma_kernel(float* __restrict__ out) {
    extern __shared__ float sm[];
    const uint32_t sbase = smem_u32(sm);
    const int tid  = threadIdx.x;
    const int wid  = tid >> 5, lane = tid & 31;
    const int g = lane >> 2, c = lane & 3;
    const int wn = wid & 1, wv = wid >> 1;
    const int b  = blockIdx.z;
    const int n0 = blockIdx.y * 128;
    const int v0 = blockIdx.x * 128;

    const float* pA = g_P  + ((size_t)b * Nn + n0) * Nn;
    const float* pB = g_Vm + ((size_t)b * Nn) * Vd + v0;

    float acc[4][4][4] = {};

    av_stage(sbase, 0, pA, pB, 0);
    cp_commit();

    for (int it = 0; it < Nn / 64; it++) {
        const int cur = it & 1;
        if (it + 1 < Nn / 64) {
            av_stage(sbase, cur ^ 1, pA, pB, it + 1);
            cp_commit();
            cp_wait1();
        } else {
            cp_wait0();
        }
        __syncthreads();

        const float* As = sm + (cur ? A_OFA1 : A_OFA0);
        const float* Bs = sm + (cur ? A_OFB1 : A_OFB0);

        #pragma unroll
        for (int ks = 0; ks < 8; ks++) {
            uint32_t af[4][4];
            #pragma unroll
            for (int i = 0; i < 4; i++) {
                const float* ap = As + (wn * 64 + i * 16 + g) * 68 + ks * 8 + c;
                af[i][0] = fu(ap[0]);
                af[i][1] = fu(ap[8 * 68]);
                af[i][2] = fu(ap[4]);
                af[i][3] = fu(ap[8 * 68 + 4]);
            }
            uint32_t bf[4][2];
            #pragma unroll
            for (int j = 0; j < 4; j++) {
                const float* bp = Bs + (ks * 8 + c) * 136 + wv * 32 + j * 8 + g;
                bf[j][0] = fu(bp[0]);
                bf[j][1] = fu(bp[4 * 136]);
            }
            #pragma unroll
            for (int i = 0; i < 4; i++)
                #pragma unroll
                for (int j = 0; j < 4; j++)
                    mma_tf32(acc[i][j], af[i], bf[j]);
        }
        __syncthreads();
    }

    #pragma unroll
    for (int i = 0; i < 4; i++) {
        const int n_lo = n0 + wn * 64 + i * 16 + g;
        const float linv_lo = 1.0f / g_L[(size_t)b * Nn + n_lo];
        const float linv_hi = 1.0f / g_L[(size_t)b * Nn + n_lo + 8];
        #pragma unroll
        for (int j = 0; j < 4; j++) {
            const int v = v0 + wv * 32 + j * 8 + c * 2;
            float* o0p = out + ((size_t)b * Vd + v)     * Nn + n_lo;
            float* o1p = out + ((size_t)b * Vd + v + 1) * Nn + n_lo;
            o0p[0] = acc[i][j][0] * linv_lo;
            o1p[0] = acc[i][j][1] * linv_lo;
            o0p[8] = acc[i][j][2] * linv_hi;
            o1p[8] = acc[i][j][3] * linv_hi;
        }
    }
}

// ===========================================================================
extern "C" void kernel_launch(void* const* d_in, const int* in_sizes, int n_in,
                              void* d_out, int out_size) {
    const float* x     = (const float*)d_in[0];
    const float* Wq    = (const float*)d_in[1];
    const float* bq    = (const float*)d_in[2];
    const float* Wk    = (const float*)d_in[3];
    const float* bk    = (const float*)d_in[4];
    const float* Wv    = (const float*)d_in[5];
    const float* gamma = (const float*)d_in[6];
    const float* beta  = (const float*)d_in[7];
    const float* mean  = (const float*)d_in[8];
    const float* var   = (const float*)d_in[9];
    float* out = (float*)d_out;

    float *Qhp, *Qlp, *Khp, *Klp;
    cudaGetSymbolAddress((void**)&Qhp, g_Qh);
    cudaGetSymbolAddress((void**)&Qlp, g_Ql);
    cudaGetSymbolAddress((void**)&Khp, g_Kh);
    cudaGetSymbolAddress((void**)&Klp, g_Kl);

    static int smem_set = 0;
    if (!smem_set) {
        cudaFuncSetAttribute(vproj_mma_kernel,
                             cudaFuncAttributeMaxDynamicSharedMemorySize, V_FLOATS * 4);
        cudaFuncSetAttribute(energy_mma_kernel,
                             cudaFuncAttributeMaxDynamicSharedMemorySize, E_FLOATS * 4);
        cudaFuncSetAttribute(av_mma_kernel,
                             cudaFuncAttributeMaxDynamicSharedMemorySize, A_FLOATS * 4);
        smem_set = 1;
    }

    prep_kernel<<<1, 512>>>(gamma, beta, mean, var);

    qk_proj_kernel<<<dim3(Nn / 64, 1, Bn), 256>>>(x, Wq, bq, Qhp, Qlp);
    qk_proj_kernel<<<dim3(Nn / 64, 1, Bn), 256>>>(x, Wk, bk, Khp, Klp);
    vproj_mma_kernel<<<dim3(Vd / 128, Nn / 128, Bn), 256, V_FLOATS * 4>>>(x, Wv);

    energy_mma_kernel<<<dim3(Nn / 128, Bn), 256, E_FLOATS * 4>>>();

    av_mma_kernel<<<dim3(Vd / 128, Nn / 128, Bn), 256, A_FLOATS * 4>>>(out);
}